// round 7
// baseline (speedup 1.0000x reference)
#include <cuda_runtime.h>
#include <cuda_fp16.h>
#include <cstdint>

// Problem constants
#define NT_   128      // N*T
#define V_    1024
#define CIN_  256
#define COUT_ 64

// Scratch: theta/phi projections, fp32 (tf32-rounded), row-major [v][64].
__device__ float g_theta[NT_ * V_ * COUT_];
__device__ float g_phi[NT_ * V_ * COUT_];

__device__ __forceinline__ unsigned f2tf(float x) {
    unsigned u;
    asm("cvt.rna.tf32.f32 %0, %1;" : "=r"(u) : "f"(x));
    return u;
}

__device__ __forceinline__ void mma_tf32(float* c,
                                         float a0, float a1, float a2, float a3,
                                         float b0, float b1) {
    asm volatile(
        "mma.sync.aligned.m16n8k8.row.col.f32.tf32.tf32.f32 "
        "{%0,%1,%2,%3},{%4,%5,%6,%7},{%8,%9},{%0,%1,%2,%3};\n"
        : "+f"(c[0]), "+f"(c[1]), "+f"(c[2]), "+f"(c[3])
        : "r"(__float_as_uint(a0)), "r"(__float_as_uint(a1)),
          "r"(__float_as_uint(a2)), "r"(__float_as_uint(a3)),
          "r"(__float_as_uint(b0)), "r"(__float_as_uint(b1)));
}

__device__ __forceinline__ uint32_t smem_u32(const void* p) {
    uint32_t a;
    asm("{ .reg .u64 t; cvta.to.shared.u64 t, %1; cvt.u32.u64 %0, t; }"
        : "=r"(a) : "l"(p));
    return a;
}
__device__ __forceinline__ void cp16s(uint32_t daddr, const float* src) {
    asm volatile("cp.async.cg.shared.global [%0], [%1], 16;\n" :: "r"(daddr), "l"(src));
}
__device__ __forceinline__ void cp_commit() { asm volatile("cp.async.commit_group;\n"); }
__device__ __forceinline__ void cp_wait0() { asm volatile("cp.async.wait_group 0;\n" ::: "memory"); }
__device__ __forceinline__ void cp_wait1() { asm volatile("cp.async.wait_group 1;\n" ::: "memory"); }

// ============================================================================
// Kernel 1: projection. Block: 128 v-rows x 128 out-cols (theta|phi), 256 thr.
// 82KB smem -> 2 CTAs/SM. Warps: wm = wid&3 (32 rows), wn = wid>>2 (64 cols).
// ============================================================================
#define PJ_SR     40                       // smem row stride (words) per 32-k chunk
#define PJ_A_SZ   (128 * PJ_SR)            // words (A and B tiles same size)
#define PJ_BUF    (2 * PJ_A_SZ)
#define PJ_SMEM_BYTES (2 * PJ_BUF * 4)     // 81920 B

__global__ void __launch_bounds__(256, 2) proj_kernel(
    const float* __restrict__ z, const float* __restrict__ tw,
    const float* __restrict__ tb, const float* __restrict__ pw,
    const float* __restrict__ pb)
{
    extern __shared__ float psm[];
    __shared__ float bias_s[128];

    const int tid = threadIdx.x, lane = tid & 31, wid = tid >> 5;
    const int g = lane >> 2, t = lane & 3;
    const int wm = wid & 3, wn = wid >> 2;
    const int nt = blockIdx.y;
    const int vbase = blockIdx.x * 128;

    if (tid < 128) bias_s[tid] = (tid < 64) ? tb[tid] : pb[tid - 64];

    const float* zb = z + (size_t)(nt * V_ + vbase) * CIN_;
    const uint32_t sb = smem_u32(psm);

    // stage chunk c into buffer b: A = z[128 x 32], B = Wcat[128 x 32]
    auto stage = [&](int c, int b) {
        const uint32_t ab = sb + (uint32_t)(b * PJ_BUF) * 4u;
        const uint32_t bb = ab + (uint32_t)PJ_A_SZ * 4u;
        const int kc = c * 32;
        #pragma unroll
        for (int p = 0; p < 4; p++) {
            int lin = tid + 256 * p;          // 0..1023: A 16B chunks
            int r = lin >> 3, c8 = lin & 7;
            cp16s(ab + (uint32_t)(r * PJ_SR * 4 + c8 * 16),
                  zb + (size_t)r * CIN_ + kc + c8 * 4);
        }
        #pragma unroll
        for (int p = 0; p < 4; p++) {
            int lin = tid + 256 * p;          // 0..1023: B 16B chunks
            int r = lin >> 3, c8 = lin & 7;
            const float* src = (r < 64) ? (tw + (size_t)r * CIN_)
                                        : (pw + (size_t)(r - 64) * CIN_);
            cp16s(bb + (uint32_t)(r * PJ_SR * 4 + c8 * 16), src + kc + c8 * 4);
        }
        cp_commit();
    };

    float acc[2][8][4];
    #pragma unroll
    for (int i = 0; i < 2; i++)
        #pragma unroll
        for (int j = 0; j < 8; j++)
            #pragma unroll
            for (int k = 0; k < 4; k++) acc[i][j][k] = 0.f;

    stage(0, 0);
    for (int c = 0; c < 8; c++) {
        if (c < 7) stage(c + 1, (c + 1) & 1);
        if (c < 7) cp_wait1(); else cp_wait0();
        __syncthreads();
        const float* A = psm + (c & 1) * PJ_BUF;
        const float* B = A + PJ_A_SZ;

        #pragma unroll
        for (int ks = 0; ks < 4; ks++) {
            const int ko = ks * 8 + 2 * t;
            float2 a0[2], a1[2];
            #pragma unroll
            for (int mf = 0; mf < 2; mf++) {
                a0[mf] = *(const float2*)&A[(wm * 32 + mf * 16 + g) * PJ_SR + ko];
                a1[mf] = *(const float2*)&A[(wm * 32 + mf * 16 + 8 + g) * PJ_SR + ko];
            }
            #pragma unroll
            for (int nf = 0; nf < 8; nf++) {
                float2 bf = *(const float2*)&B[(wn * 64 + nf * 8 + g) * PJ_SR + ko];
                #pragma unroll
                for (int mf = 0; mf < 2; mf++)
                    mma_tf32(acc[mf][nf], a0[mf].x, a1[mf].x, a0[mf].y, a1[mf].y,
                             bf.x, bf.y);
            }
        }
        __syncthreads();
    }

    // Epilogue: bias, tf32-round, float2 stores. wn=0 -> theta, wn=1 -> phi.
    float* dst = wn ? g_phi : g_theta;
    #pragma unroll
    for (int mf = 0; mf < 2; mf++) {
        const int row0 = vbase + wm * 32 + mf * 16 + g;
        #pragma unroll
        for (int nf = 0; nf < 8; nf++) {
            int c = nf * 8 + 2 * t;
            float b0 = bias_s[wn * 64 + c], b1 = bias_s[wn * 64 + c + 1];
            float2 v0 = make_float2(__uint_as_float(f2tf(acc[mf][nf][0] + b0)),
                                    __uint_as_float(f2tf(acc[mf][nf][1] + b1)));
            float2 v1 = make_float2(__uint_as_float(f2tf(acc[mf][nf][2] + b0)),
                                    __uint_as_float(f2tf(acc[mf][nf][3] + b1)));
            *(float2*)&dst[((size_t)(nt * V_) + row0) * COUT_ + c] = v0;
            *(float2*)&dst[((size_t)(nt * V_) + row0 + 8) * COUT_ + c] = v1;
        }
    }
}

// ============================================================================
// Kernel 2: single-exp softmax-GEMM, 2 CTAs/SM.
// Block: 32 theta rows x 1024 cols, 256 threads (2 m-warps x 4 n-warps).
// Theta fragments in registers. 16 phi chunks of 64 rows, double-buffered.
// SMEM: E 32x520 u32 (66.6KB) + phi 2x64x72 f32 (36.9KB) = 103.4KB.
// ============================================================================
#define ESTRIDE  520                       // u32 words per row
#define BSR      72                        // phi buf row stride (words)
#define PBUF_W   (64 * BSR)
#define ADJ_SMEM_BYTES ((32 * ESTRIDE + 2 * PBUF_W) * 4)

__global__ void __launch_bounds__(256, 2) adj_kernel(float* __restrict__ G)
{
    extern __shared__ unsigned asm_[];
    unsigned* E = asm_;                         // 32 x ESTRIDE
    float* P = (float*)(asm_ + 32 * ESTRIDE);   // 2 x 64 x BSR
    __shared__ float red[128];
    __shared__ float invs[32];

    const int tid = threadIdx.x, lane = tid & 31, wid = tid >> 5;
    const int g = lane >> 2, t = lane & 3;
    const int wm = wid & 1;     // 2 m-warps x 16 rows
    const int wn = wid >> 1;    // 4 n-warps x 16 cols (per 64-col chunk)
    const int nt = blockIdx.x >> 5;
    const int vbase = (blockIdx.x & 31) * 32;

    const float* th = g_theta + (size_t)(nt * V_ + vbase) * COUT_;
    const float* ph = g_phi + (size_t)nt * V_ * COUT_;
    const uint32_t pbase = smem_u32(P);

    // theta fragments -> registers: rows wm*16 + g + 8h
    float2 a[2][8];
    #pragma unroll
    for (int h = 0; h < 2; h++)
        #pragma unroll
        for (int ks = 0; ks < 8; ks++)
            a[h][ks] = *(const float2*)&th[
                (size_t)(wm * 16 + g + 8 * h) * COUT_ + ks * 8 + 2 * t];

    auto stage = [&](int c, int b) {
        const uint32_t dst = pbase + (uint32_t)(b * PBUF_W) * 4u;
        const float* src = ph + (size_t)c * 64 * COUT_;
        #pragma unroll
        for (int p = 0; p < 4; p++) {
            int lin = tid + 256 * p;          // 0..1023
            int r = lin >> 4, c4 = lin & 15;
            cp16s(dst + (uint32_t)(r * BSR * 4 + c4 * 16),
                  src + (size_t)r * COUT_ + c4 * 4);
        }
        cp_commit();
    };

    stage(0, 0);
    float rowsum[2] = {0.f, 0.f};

    // ---------------- PASS 1 ----------------
    for (int c = 0; c < 16; c++) {
        if (c < 15) stage(c + 1, (c + 1) & 1);
        if (c < 15) cp_wait1(); else cp_wait0();
        __syncthreads();
        const float* B = P + (c & 1) * PBUF_W;

        float acc[2][4];
        #pragma unroll
        for (int j = 0; j < 2; j++)
            #pragma unroll
            for (int k = 0; k < 4; k++) acc[j][k] = 0.f;

        #pragma unroll
        for (int ks = 0; ks < 8; ks++) {
            const int ko = ks * 8 + 2 * t;
            float2 b0 = *(const float2*)&B[(wn * 16 + g) * BSR + ko];
            float2 b1 = *(const float2*)&B[(wn * 16 + 8 + g) * BSR + ko];
            mma_tf32(acc[0], a[0][ks].x, a[1][ks].x, a[0][ks].y, a[1][ks].y,
                     b0.x, b0.y);
            mma_tf32(acc[1], a[0][ks].x, a[1][ks].x, a[0][ks].y, a[1][ks].y,
                     b1.x, b1.y);
        }

        // exp + fp16 store + rowsums
        #pragma unroll
        for (int nf = 0; nf < 2; nf++) {
            float e0 = __expf(acc[nf][0]);
            float e1 = __expf(acc[nf][1]);
            float e2 = __expf(acc[nf][2]);
            float e3 = __expf(acc[nf][3]);
            rowsum[0] += e0 + e1;
            rowsum[1] += e2 + e3;
            int col2 = c * 32 + wn * 8 + nf * 4 + t;
            int r0 = wm * 16 + g;
            __half2 h0 = __floats2half2_rn(e0, e1);
            __half2 h1 = __floats2half2_rn(e2, e3);
            E[r0 * ESTRIDE + col2] = *(unsigned*)&h0;
            E[(r0 + 8) * ESTRIDE + col2] = *(unsigned*)&h1;
        }
        __syncthreads();
    }

    // ---------------- row-sum reduction ----------------
    #pragma unroll
    for (int i = 0; i < 2; i++) {
        float s = rowsum[i];
        s += __shfl_xor_sync(0xffffffffu, s, 1);
        s += __shfl_xor_sync(0xffffffffu, s, 2);
        if (t == 0)
            red[wn * 32 + wm * 16 + i * 8 + g] = s;
    }
    __syncthreads();
    if (tid < 32) {
        float s = red[tid] + red[32 + tid] + red[64 + tid] + red[96 + tid];
        invs[tid] = 1.0f / s;
    }
    __syncthreads();

    // ---------------- PASS 2: scale + write (uint4 E reads) ----------------
    const int row = tid >> 3;            // 0..31
    const int c2b = tid & 7;
    const float iv = invs[row];
    float* grow = G + ((size_t)(nt * V_ + vbase + row)) * V_;
    const uint4* er = (const uint4*)(E + row * ESTRIDE);
    #pragma unroll 4
    for (int j = 0; j < 16; j++) {
        uint4 u = er[c2b + 8 * j];       // 8 fp16 = cols 8*c2b+64*j .. +7
        float2 f0 = __half22float2(*(__half2*)&u.x);
        float2 f1 = __half22float2(*(__half2*)&u.y);
        float2 f2 = __half22float2(*(__half2*)&u.z);
        float2 f3 = __half22float2(*(__half2*)&u.w);
        float4 o0 = make_float4(f0.x * iv, f0.y * iv, f1.x * iv, f1.y * iv);
        float4 o1 = make_float4(f2.x * iv, f2.y * iv, f3.x * iv, f3.y * iv);
        float* dst = grow + 8 * c2b + 64 * j;
        *(float4*)dst = o0;
        *(float4*)(dst + 4) = o1;
    }
}

// ============================================================================
extern "C" void kernel_launch(void* const* d_in, const int* in_sizes, int n_in,
                              void* d_out, int out_size)
{
    const float* z  = (const float*)d_in[0];
    const float* tw = (const float*)d_in[1];
    const float* tb = (const float*)d_in[2];
    const float* pw = (const float*)d_in[3];
    const float* pb = (const float*)d_in[4];
    float* G = (float*)d_out;

    cudaFuncSetAttribute(proj_kernel, cudaFuncAttributeMaxDynamicSharedMemorySize,
                         PJ_SMEM_BYTES);
    proj_kernel<<<dim3(V_ / 128, NT_), 256, PJ_SMEM_BYTES>>>(z, tw, tb, pw, pb);

    cudaFuncSetAttribute(adj_kernel, cudaFuncAttributeMaxDynamicSharedMemorySize,
                         ADJ_SMEM_BYTES);
    adj_kernel<<<NT_ * 32, 256, ADJ_SMEM_BYTES>>>(G);
}